// round 3
// baseline (speedup 1.0000x reference)
#include <cuda_runtime.h>
#include <math.h>

#define N_TOK   131072
#define K_CODES 512
#define DIM     64
#define M_ELEMS (N_TOK * DIM)
#define TPB     512
#define NBLK    (N_TOK / TPB)

__device__ float        g_sumsq;
__device__ unsigned int g_counts[K_CODES];

__global__ void vq_init_kernel() {
    int t = threadIdx.x;
    if (t == 0) g_sumsq = 0.0f;
    if (t < K_CODES) g_counts[t] = 0u;
}

// ---------------------------------------------------------------------------
// SMEM: pair-interleaved codebook spw[256 kpairs][32 dpairs] as float4
//       {w[2kk][2dd], w[2kk+1][2dd], w[2kk][2dd+1], w[2kk+1][2dd+1]}  (128 KB)
//       + C[512] + sidx[512] + hist[512]
// Each f32x2 lane carries ONE code's sequential IEEE fp32 FMA chain over d
// ascending — bit-identical to a scalar fmaf chain (reference BLAS order).
// ---------------------------------------------------------------------------
extern "C" __global__ void __launch_bounds__(TPB, 1)
vq_main_kernel(const float* __restrict__ in,
               const float* __restrict__ wt,
               float* __restrict__ out)
{
    extern __shared__ float smem[];
    float4*       spw   = (float4*)smem;                    // [256][32]
    float*        sC    = smem + K_CODES * DIM;             // [512]
    int*          sidx  = (int*)(sC + K_CODES);             // [512]
    unsigned int* shist = (unsigned int*)(sidx + TPB);      // [512]

    const int tid = threadIdx.x;

    // Build pair-interleaved codebook
    for (int i = tid; i < 256 * 32; i += TPB) {
        int kk = i >> 5, dd = i & 31;
        const float2* r0 = (const float2*)(wt + (2 * kk)     * DIM);
        const float2* r1 = (const float2*)(wt + (2 * kk + 1) * DIM);
        float2 a = r0[dd], b = r1[dd];
        spw[i] = make_float4(a.x, b.x, a.y, b.y);
    }
    for (int i = tid; i < K_CODES; i += TPB) shist[i] = 0u;
    __syncthreads();

    // C_k = sum_d w^2  (rounded square, sequential adds, d ascending)
    for (int k = tid; k < K_CODES; k += TPB) {
        float s = 0.0f;
        for (int d = 0; d < DIM; d++) {
            float v = smem[((k >> 1) * 32 + (d >> 1)) * 4 + (d & 1) * 2 + (k & 1)];
            s = __fadd_rn(s, __fmul_rn(v, v));
        }
        sC[k] = s;
    }
    __syncthreads();

    // Token n = b*4096 + hw ; x[d] = in[(b<<18) + (d<<12) + hw]
    const int n  = blockIdx.x * TPB + tid;
    const int b  = n >> 12;
    const int hw = n & 4095;
    const float* base = in + (b << 18) + hw;

    float xr[DIM];
    #pragma unroll
    for (int d = 0; d < DIM; d++) xr[d] = base[d << 12];

    // A = sum_d x^2 (rounded square, sequential adds, d ascending)
    float A = 0.0f;
    #pragma unroll
    for (int d = 0; d < DIM; d++) A = __fadd_rn(A, __fmul_rn(xr[d], xr[d]));

    // Pre-broadcast x pairs into 64-bit registers {x[d], x[d]} once.
    unsigned long long xb[DIM];
    #pragma unroll
    for (int d = 0; d < DIM; d++)
        asm("mov.b64 %0, {%1, %1};" : "=l"(xb[d]) : "f"(xr[d]));

    // Argmin over rounded distances d_k = (A - 2*dot_k) + C_k
    float best = 3.4e38f;
    int   bidx = 0;
    for (int kkg = 0; kkg < 128; kkg++) {
        unsigned long long acc0, acc1;
        asm("mov.b64 %0, {%1, %1};" : "=l"(acc0) : "f"(0.0f));
        asm("mov.b64 %0, {%1, %1};" : "=l"(acc1) : "f"(0.0f));
        const float4* p0 = spw + (2 * kkg)     * 32;
        const float4* p1 = spw + (2 * kkg + 1) * 32;
        #pragma unroll
        for (int dd = 0; dd < 32; dd++) {
            float4 v0 = p0[dd];
            float4 v1 = p1[dd];
            unsigned long long w00, w01, w10, w11;
            asm("mov.b64 %0, {%1, %2};" : "=l"(w00) : "f"(v0.x), "f"(v0.y));
            asm("mov.b64 %0, {%1, %2};" : "=l"(w01) : "f"(v0.z), "f"(v0.w));
            asm("mov.b64 %0, {%1, %2};" : "=l"(w10) : "f"(v1.x), "f"(v1.y));
            asm("mov.b64 %0, {%1, %2};" : "=l"(w11) : "f"(v1.z), "f"(v1.w));
            asm("fma.rn.f32x2 %0, %1, %2, %0;" : "+l"(acc0) : "l"(xb[2 * dd]),     "l"(w00));
            asm("fma.rn.f32x2 %0, %1, %2, %0;" : "+l"(acc0) : "l"(xb[2 * dd + 1]), "l"(w01));
            asm("fma.rn.f32x2 %0, %1, %2, %0;" : "+l"(acc1) : "l"(xb[2 * dd]),     "l"(w10));
            asm("fma.rn.f32x2 %0, %1, %2, %0;" : "+l"(acc1) : "l"(xb[2 * dd + 1]), "l"(w11));
        }
        float m0, m1, m2, m3;
        asm("mov.b64 {%0, %1}, %2;" : "=f"(m0), "=f"(m1) : "l"(acc0));
        asm("mov.b64 {%0, %1}, %2;" : "=f"(m2), "=f"(m3) : "l"(acc1));
        const int kb = 4 * kkg;
        // evaluate in ascending k with strict < (argmin first-index tie-break)
        float d0 = __fadd_rn(__fadd_rn(A, -2.0f * m0), sC[kb]);
        if (d0 < best) { best = d0; bidx = kb; }
        float d1 = __fadd_rn(__fadd_rn(A, -2.0f * m1), sC[kb + 1]);
        if (d1 < best) { best = d1; bidx = kb + 1; }
        float d2 = __fadd_rn(__fadd_rn(A, -2.0f * m2), sC[kb + 2]);
        if (d2 < best) { best = d2; bidx = kb + 2; }
        float d3 = __fadd_rn(__fadd_rn(A, -2.0f * m3), sC[kb + 3]);
        if (d3 < best) { best = d3; bidx = kb + 3; }
    }

    sidx[tid] = bidx;
    atomicAdd(&shist[bidx], 1u);
    __syncthreads();

    // Output + loss partial: quantized rows viewed LINEARLY into input shape
    float lsum = 0.0f;
    const long outBase = (long)blockIdx.x * TPB * DIM;
    for (int i = tid; i < TPB * DIM; i += TPB) {
        int   tok = i >> 6;
        int   d   = i & 63;
        int   k   = sidx[tok];
        float q   = smem[((k >> 1) * 32 + (d >> 1)) * 4 + (d & 1) * 2 + (k & 1)];
        float xv  = in[outBase + i];
        out[outBase + i] = q;
        float df = q - xv;
        lsum = fmaf(df, df, lsum);
    }

    #pragma unroll
    for (int o = 16; o > 0; o >>= 1) lsum += __shfl_xor_sync(0xffffffffu, lsum, o);
    const int lane = tid & 31, wrp = tid >> 5;
    __syncthreads();
    if (lane == 0) sC[wrp] = lsum;   // reuse sC as scratch
    __syncthreads();
    if (wrp == 0) {
        float v = (lane < TPB / 32) ? sC[lane] : 0.0f;
        #pragma unroll
        for (int o = 8; o > 0; o >>= 1) v += __shfl_xor_sync(0xffffffffu, v, o);
        if (lane == 0) atomicAdd(&g_sumsq, v);
    }

    for (int k = tid; k < K_CODES; k += TPB) {
        unsigned int c = shist[k];
        if (c) atomicAdd(&g_counts[k], c);
    }
}

__global__ void vq_final_kernel(float* __restrict__ out) {
    int t = threadIdx.x;  // 512 threads
    float p    = (float)g_counts[t] * (1.0f / (float)N_TOK);
    float term = p * logf(p + 1e-10f);
    #pragma unroll
    for (int o = 16; o > 0; o >>= 1) term += __shfl_xor_sync(0xffffffffu, term, o);
    __shared__ float r[16];
    if ((t & 31) == 0) r[t >> 5] = term;
    __syncthreads();
    if (t < 16) {
        float v = r[t];
        #pragma unroll
        for (int o = 8; o > 0; o >>= 1) v += __shfl_xor_sync(0x0000ffffu, v, o);
        if (t == 0) {
            out[M_ELEMS]     = 1.25f * (g_sumsq * (1.0f / (float)M_ELEMS));
            out[M_ELEMS + 1] = expf(-v);
        }
    }
}

extern "C" void kernel_launch(void* const* d_in, const int* in_sizes, int n_in,
                              void* d_out, int out_size)
{
    const float* in  = (const float*)d_in[0];
    const float* wt  = (const float*)d_in[1];
    float*       out = (float*)d_out;

    const int smem_bytes = (K_CODES * DIM + K_CODES) * 4 + TPB * 4 + K_CODES * 4;
    cudaFuncSetAttribute(vq_main_kernel,
                         cudaFuncAttributeMaxDynamicSharedMemorySize, smem_bytes);

    vq_init_kernel<<<1, 512>>>();
    vq_main_kernel<<<NBLK, TPB, smem_bytes>>>(in, wt, out);
    vq_final_kernel<<<1, 512>>>(out);
}

// round 4
// speedup vs baseline: 1.1276x; 1.1276x over previous
#include <cuda_runtime.h>
#include <math.h>

#define N_TOK   131072
#define K_CODES 512
#define DIM     64
#define M_ELEMS (N_TOK * DIM)
#define TPB     256
#define NBLK    148              // persistent: one block per SM
#define MAXTOK  896              // max tokens per block (886 actual)

typedef unsigned long long ull;

__device__ float        g_sumsq;     // zero-initialized at load; final kernel re-zeroes
__device__ unsigned int g_counts[K_CODES];

// ---------------------------------------------------------------------------
// Main kernel. SMEM: pair-interleaved codebook spw[256 kpairs][32 dpairs] as
// float4 {w[2kk][2dd], w[2kk+1][2dd], w[2kk][2dd+1], w[2kk+1][2dd+1]} (128KB)
// + C[512] + sidx[896] + hist[512].
// Each f32x2 lane carries ONE code's sequential IEEE fp32 FMA chain over d
// ascending — bit-identical to the reference BLAS accumulation order.
// ---------------------------------------------------------------------------
extern "C" __global__ void __launch_bounds__(TPB, 1)
vq_main_kernel(const float* __restrict__ in,
               const float* __restrict__ wt,
               float* __restrict__ out)
{
    extern __shared__ float smem[];
    float4*       spw   = (float4*)smem;                    // [256][32] = 128KB
    float*        sC    = smem + K_CODES * DIM;             // [512]
    int*          sidx  = (int*)(sC + K_CODES);             // [896]
    unsigned int* shist = (unsigned int*)(sidx + MAXTOK);   // [512]

    const int tid = threadIdx.x;
    const int bid = blockIdx.x;

    // Token range for this block: blocks 0..91 get 886 tokens, 92..147 get 885
    const int start = bid * 885 + min(bid, 92);
    const int end   = start + 885 + (bid < 92 ? 1 : 0);
    const int ntok  = end - start;

    // Stage pair-interleaved codebook
    for (int i = tid; i < 256 * 32; i += TPB) {
        int kk = i >> 5, dd = i & 31;
        const float2* r0 = (const float2*)(wt + (2 * kk)     * DIM);
        const float2* r1 = (const float2*)(wt + (2 * kk + 1) * DIM);
        float2 a = r0[dd], b = r1[dd];
        spw[i] = make_float4(a.x, b.x, a.y, b.y);
    }
    for (int i = tid; i < K_CODES; i += TPB) shist[i] = 0u;
    __syncthreads();

    // C_k = sum_d w^2 (rounded square, sequential adds, d ascending)
    for (int k = tid; k < K_CODES; k += TPB) {
        float s = 0.0f;
        for (int d = 0; d < DIM; d++) {
            float v = smem[((k >> 1) * 32 + (d >> 1)) * 4 + (d & 1) * 2 + (k & 1)];
            s = __fadd_rn(s, __fmul_rn(v, v));
        }
        sC[k] = s;
    }
    __syncthreads();

    const unsigned swb = (unsigned)__cvta_generic_to_shared(spw);

    // ---- per-token argmin (thread-strided over the block's range) ----
    for (int t = start + tid; t < end; t += TPB) {
        const int b  = t >> 12;
        const int hw = t & 4095;
        const float* base = in + (b << 18) + hw;

        // Gather x; A = sum x^2 (sequential); xb[d] = {x[d], x[d]} packed
        float A = 0.0f;
        ull xb[DIM];
        #pragma unroll
        for (int d = 0; d < DIM; d++) {
            float f = base[d << 12];
            A = __fadd_rn(A, __fmul_rn(f, f));
            asm("mov.b64 %0, {%1, %1};" : "=l"(xb[d]) : "f"(f));
        }

        float best = 3.4e38f;
        int   bidx = 0;
        for (int kkg = 0; kkg < 128; kkg++) {
            const unsigned a0 = swb + kkg * 1024;   // code pair 2kkg   (32 float4)
            const unsigned a1 = a0 + 512;           // code pair 2kkg+1
            ull acc0 = 0ULL, acc1 = 0ULL;           // {0.0f, 0.0f}
            #pragma unroll
            for (int dd = 0; dd < 32; dd++) {
                ull w00, w01, w10, w11;
                asm("ld.shared.v2.u64 {%0,%1}, [%2];"
                    : "=l"(w00), "=l"(w01) : "r"(a0 + dd * 16));
                asm("ld.shared.v2.u64 {%0,%1}, [%2];"
                    : "=l"(w10), "=l"(w11) : "r"(a1 + dd * 16));
                asm("fma.rn.f32x2 %0, %1, %2, %0;" : "+l"(acc0) : "l"(xb[2*dd]),   "l"(w00));
                asm("fma.rn.f32x2 %0, %1, %2, %0;" : "+l"(acc0) : "l"(xb[2*dd+1]), "l"(w01));
                asm("fma.rn.f32x2 %0, %1, %2, %0;" : "+l"(acc1) : "l"(xb[2*dd]),   "l"(w10));
                asm("fma.rn.f32x2 %0, %1, %2, %0;" : "+l"(acc1) : "l"(xb[2*dd+1]), "l"(w11));
            }
            float m0, m1, m2, m3;
            asm("mov.b64 {%0, %1}, %2;" : "=f"(m0), "=f"(m1) : "l"(acc0));
            asm("mov.b64 {%0, %1}, %2;" : "=f"(m2), "=f"(m3) : "l"(acc1));
            const int kb = 4 * kkg;
            // ascending k, strict < : argmin first-index tie-break
            float d0 = __fadd_rn(__fadd_rn(A, -2.0f * m0), sC[kb]);
            if (d0 < best) { best = d0; bidx = kb; }
            float d1 = __fadd_rn(__fadd_rn(A, -2.0f * m1), sC[kb + 1]);
            if (d1 < best) { best = d1; bidx = kb + 1; }
            float d2 = __fadd_rn(__fadd_rn(A, -2.0f * m2), sC[kb + 2]);
            if (d2 < best) { best = d2; bidx = kb + 2; }
            float d3 = __fadd_rn(__fadd_rn(A, -2.0f * m3), sC[kb + 3]);
            if (d3 < best) { best = d3; bidx = kb + 3; }
        }

        sidx[t - start] = bidx;
        atomicAdd(&shist[bidx], 1u);
    }
    __syncthreads();

    // ---- output + loss partial (quantized rows viewed LINEARLY into input) ----
    float lsum = 0.0f;
    const long outBase = (long)start * DIM;
    const int  nelem   = ntok * DIM;
    for (int i = tid; i < nelem; i += TPB) {
        int   tok = i >> 6;
        int   d   = i & 63;
        int   k   = sidx[tok];
        float q   = smem[((k >> 1) * 32 + (d >> 1)) * 4 + (d & 1) * 2 + (k & 1)];
        float xv  = in[outBase + i];
        out[outBase + i] = q;
        float df = q - xv;
        lsum = fmaf(df, df, lsum);
    }

    #pragma unroll
    for (int o = 16; o > 0; o >>= 1) lsum += __shfl_xor_sync(0xffffffffu, lsum, o);
    const int lane = tid & 31, wrp = tid >> 5;
    __syncthreads();
    if (lane == 0) sC[wrp] = lsum;        // reuse sC as scratch
    __syncthreads();
    if (wrp == 0) {
        float v = (lane < TPB / 32) ? sC[lane] : 0.0f;
        #pragma unroll
        for (int o = 4; o > 0; o >>= 1) v += __shfl_xor_sync(0xffffffffu, v, o);
        if (lane == 0) atomicAdd(&g_sumsq, v);
    }

    for (int k = tid; k < K_CODES; k += TPB) {
        unsigned int c = shist[k];
        if (c) atomicAdd(&g_counts[k], c);
    }
}

// ---------------------------------------------------------------------------
// Final: loss + perplexity, then reset accumulators for the next graph replay
// ---------------------------------------------------------------------------
__global__ void vq_final_kernel(float* __restrict__ out) {
    int t = threadIdx.x;  // 512 threads
    unsigned int cnt = g_counts[t];
    float p    = (float)cnt * (1.0f / (float)N_TOK);
    float term = p * logf(p + 1e-10f);
    #pragma unroll
    for (int o = 16; o > 0; o >>= 1) term += __shfl_xor_sync(0xffffffffu, term, o);
    __shared__ float r[16];
    if ((t & 31) == 0) r[t >> 5] = term;
    __syncthreads();
    if (t < 16) {
        float v = r[t];
        #pragma unroll
        for (int o = 8; o > 0; o >>= 1) v += __shfl_xor_sync(0x0000ffffu, v, o);
        if (t == 0) {
            out[M_ELEMS]     = 1.25f * (g_sumsq * (1.0f / (float)M_ELEMS));
            out[M_ELEMS + 1] = expf(-v);
            g_sumsq = 0.0f;               // reset for next replay
        }
    }
    g_counts[t] = 0u;                     // reset for next replay
}

extern "C" void kernel_launch(void* const* d_in, const int* in_sizes, int n_in,
                              void* d_out, int out_size)
{
    const float* in  = (const float*)d_in[0];
    const float* wt  = (const float*)d_in[1];
    float*       out = (float*)d_out;

    const int smem_bytes = (K_CODES * DIM + K_CODES) * 4 + MAXTOK * 4 + K_CODES * 4;
    cudaFuncSetAttribute(vq_main_kernel,
                         cudaFuncAttributeMaxDynamicSharedMemorySize, smem_bytes);

    vq_main_kernel<<<NBLK, TPB, smem_bytes>>>(in, wt, out);
    vq_final_kernel<<<1, 512>>>(out);
}

// round 5
// speedup vs baseline: 1.1811x; 1.0474x over previous
#include <cuda_runtime.h>
#include <math.h>

#define N_TOK   131072
#define K_CODES 512
#define DIM     64
#define M_ELEMS (N_TOK * DIM)
#define TPB     512
#define NBLK    148              // persistent: one block per SM
#define MAXTOK  896              // max tokens per block (886 actual)

typedef unsigned long long ull;

__device__ float        g_sumsq;     // zeroed at load; final kernel re-zeroes each replay
__device__ unsigned int g_counts[K_CODES];

// ---------------------------------------------------------------------------
// SMEM: pair-interleaved codebook spw[256 kpairs][32 dpairs] as float4
//       {w[2kk][2dd], w[2kk+1][2dd], w[2kk][2dd+1], w[2kk+1][2dd+1]} (128KB)
//       + C[512] + sidx[896] + hist[512]
// Each f32x2 lane carries ONE code's sequential IEEE fp32 FMA chain over d
// ascending — bit-identical to the reference BLAS accumulation order.
// ---------------------------------------------------------------------------
extern "C" __global__ void __launch_bounds__(TPB, 1)
vq_main_kernel(const float* __restrict__ in,
               const float* __restrict__ wt,
               float* __restrict__ out)
{
    extern __shared__ float smem[];
    float4*       spw   = (float4*)smem;                    // [256][32] = 128KB
    float*        sC    = smem + K_CODES * DIM;             // [512]
    int*          sidx  = (int*)(sC + K_CODES);             // [896]
    unsigned int* shist = (unsigned int*)(sidx + MAXTOK);   // [512]

    const int tid = threadIdx.x;
    const int bid = blockIdx.x;

    // Token range: blocks 0..91 get 886 tokens, 92..147 get 885 (148*885+92=131072)
    const int start = bid * 885 + min(bid, 92);
    const int end   = start + 885 + (bid < 92 ? 1 : 0);
    const int ntok  = end - start;

    // Stage pair-interleaved codebook
    for (int i = tid; i < 256 * 32; i += TPB) {
        int kk = i >> 5, dd = i & 31;
        const float2* r0 = (const float2*)(wt + (2 * kk)     * DIM);
        const float2* r1 = (const float2*)(wt + (2 * kk + 1) * DIM);
        float2 a = r0[dd], b = r1[dd];
        spw[i] = make_float4(a.x, b.x, a.y, b.y);
    }
    for (int i = tid; i < K_CODES; i += TPB) shist[i] = 0u;
    __syncthreads();

    // C_k = sum_d w^2 (rounded square, sequential adds, d ascending)
    for (int k = tid; k < K_CODES; k += TPB) {
        float s = 0.0f;
        for (int d = 0; d < DIM; d++) {
            float v = smem[((k >> 1) * 32 + (d >> 1)) * 4 + (d & 1) * 2 + (k & 1)];
            s = __fadd_rn(s, __fmul_rn(v, v));
        }
        sC[k] = s;
    }
    __syncthreads();

    const unsigned swb = (unsigned)__cvta_generic_to_shared(spw);

    // ---- per-token argmin (thread-strided over the block's range) ----
    for (int t = start + tid; t < end; t += TPB) {
        const int b  = t >> 12;
        const int hw = t & 4095;
        const float* base = in + (b << 18) + hw;

        // Gather x into 64 scalar regs; A = sum x^2 (sequential, d ascending)
        float xr[DIM];
        float A = 0.0f;
        #pragma unroll
        for (int d = 0; d < DIM; d++) {
            xr[d] = base[d << 12];
            A = __fadd_rn(A, __fmul_rn(xr[d], xr[d]));
        }

        float best = 3.4e38f;
        int   bidx = 0;
        for (int kkg = 0; kkg < 128; kkg++) {
            const unsigned a0 = swb + kkg * 1024;   // code pair 2kkg   (32 float4)
            const unsigned a1 = a0 + 512;           // code pair 2kkg+1
            ull acc0 = 0ULL, acc1 = 0ULL;           // {0.0f, 0.0f}
            #pragma unroll
            for (int dd = 0; dd < 32; dd++) {
                ull w00, w01, w10, w11, xlo, xhi;
                asm("ld.shared.v2.u64 {%0,%1}, [%2];"
                    : "=l"(w00), "=l"(w01) : "r"(a0 + dd * 16));
                asm("ld.shared.v2.u64 {%0,%1}, [%2];"
                    : "=l"(w10), "=l"(w11) : "r"(a1 + dd * 16));
                asm("mov.b64 %0, {%1, %1};" : "=l"(xlo) : "f"(xr[2 * dd]));
                asm("mov.b64 %0, {%1, %1};" : "=l"(xhi) : "f"(xr[2 * dd + 1]));
                asm("fma.rn.f32x2 %0, %1, %2, %0;" : "+l"(acc0) : "l"(xlo), "l"(w00));
                asm("fma.rn.f32x2 %0, %1, %2, %0;" : "+l"(acc0) : "l"(xhi), "l"(w01));
                asm("fma.rn.f32x2 %0, %1, %2, %0;" : "+l"(acc1) : "l"(xlo), "l"(w10));
                asm("fma.rn.f32x2 %0, %1, %2, %0;" : "+l"(acc1) : "l"(xhi), "l"(w11));
            }
            float m0, m1, m2, m3;
            asm("mov.b64 {%0, %1}, %2;" : "=f"(m0), "=f"(m1) : "l"(acc0));
            asm("mov.b64 {%0, %1}, %2;" : "=f"(m2), "=f"(m3) : "l"(acc1));
            const int kb = 4 * kkg;
            // ascending k, strict < : argmin first-index tie-break
            float d0 = __fadd_rn(__fadd_rn(A, -2.0f * m0), sC[kb]);
            if (d0 < best) { best = d0; bidx = kb; }
            float d1 = __fadd_rn(__fadd_rn(A, -2.0f * m1), sC[kb + 1]);
            if (d1 < best) { best = d1; bidx = kb + 1; }
            float d2 = __fadd_rn(__fadd_rn(A, -2.0f * m2), sC[kb + 2]);
            if (d2 < best) { best = d2; bidx = kb + 2; }
            float d3 = __fadd_rn(__fadd_rn(A, -2.0f * m3), sC[kb + 3]);
            if (d3 < best) { best = d3; bidx = kb + 3; }
        }

        sidx[t - start] = bidx;
        atomicAdd(&shist[bidx], 1u);
    }
    __syncthreads();

    // ---- output + loss partial (quantized rows viewed LINEARLY into input) ----
    float lsum = 0.0f;
    const long outBase = (long)start * DIM;
    const int  nelem   = ntok * DIM;
    for (int i = tid; i < nelem; i += TPB) {
        int   tok = i >> 6;
        int   d   = i & 63;
        int   k   = sidx[tok];
        float q   = smem[((k >> 1) * 32 + (d >> 1)) * 4 + (d & 1) * 2 + (k & 1)];
        float xv  = in[outBase + i];
        out[outBase + i] = q;
        float df = q - xv;
        lsum = fmaf(df, df, lsum);
    }

    #pragma unroll
    for (int o = 16; o > 0; o >>= 1) lsum += __shfl_xor_sync(0xffffffffu, lsum, o);
    const int lane = tid & 31, wrp = tid >> 5;
    __syncthreads();
    if (lane == 0) sC[wrp] = lsum;        // reuse sC as scratch
    __syncthreads();
    if (wrp == 0) {
        float v = (lane < TPB / 32) ? sC[lane] : 0.0f;
        #pragma unroll
        for (int o = 8; o > 0; o >>= 1) v += __shfl_xor_sync(0xffffffffu, v, o);
        if (lane == 0) atomicAdd(&g_sumsq, v);
    }

    for (int k = tid; k < K_CODES; k += TPB) {
        unsigned int c = shist[k];
        if (c) atomicAdd(&g_counts[k], c);
    }
}

// ---------------------------------------------------------------------------
// Final: loss + perplexity, then reset accumulators for the next graph replay
// ---------------------------------------------------------------------------
__global__ void vq_final_kernel(float* __restrict__ out) {
    int t = threadIdx.x;  // 512 threads
    unsigned int cnt = g_counts[t];
    float p    = (float)cnt * (1.0f / (float)N_TOK);
    float term = p * logf(p + 1e-10f);
    #pragma unroll
    for (int o = 16; o > 0; o >>= 1) term += __shfl_xor_sync(0xffffffffu, term, o);
    __shared__ float r[16];
    if ((t & 31) == 0) r[t >> 5] = term;
    __syncthreads();
    if (t < 16) {
        float v = r[t];
        #pragma unroll
        for (int o = 8; o > 0; o >>= 1) v += __shfl_xor_sync(0x0000ffffu, v, o);
        if (t == 0) {
            out[M_ELEMS]     = 1.25f * (g_sumsq * (1.0f / (float)M_ELEMS));
            out[M_ELEMS + 1] = expf(-v);
            g_sumsq = 0.0f;               // reset for next replay
        }
    }
    g_counts[t] = 0u;                     // reset for next replay
}

extern "C" void kernel_launch(void* const* d_in, const int* in_sizes, int n_in,
                              void* d_out, int out_size)
{
    const float* in  = (const float*)d_in[0];
    const float* wt  = (const float*)d_in[1];
    float*       out = (float*)d_out;

    const int smem_bytes = (K_CODES * DIM + K_CODES) * 4 + MAXTOK * 4 + K_CODES * 4;
    cudaFuncSetAttribute(vq_main_kernel,
                         cudaFuncAttributeMaxDynamicSharedMemorySize, smem_bytes);

    vq_main_kernel<<<NBLK, TPB, smem_bytes>>>(in, wt, out);
    vq_final_kernel<<<1, 512>>>(out);
}

// round 7
// speedup vs baseline: 1.7936x; 1.5186x over previous
#include <cuda_runtime.h>
#include <cuda_bf16.h>
#include <math.h>

#define N_TOK   131072
#define K_CODES 512
#define DIM     64
#define M_ELEMS (N_TOK * DIM)
#define TPB     256
#define TOKCTA  256
#define NCTA    (N_TOK / TOKCTA)     // 512
#define MARGIN  3.0e-3f              // >= 2x worst-case bf16 scoring error
#define CAP     16

// SMEM byte offsets (rows padded to 144B -> ldmatrix conflict-free)
#define SM_A    0                    // A tile: 256 rows x 144B (36864)
#define SM_B    36864                // B tile: 512 rows x 144B (73728)
#define SM_C    110592               // C fp32[512]
#define SM_H    112640               // hist u32[512]
#define SM_CNT  114688               // cand count u32[256]
#define SM_CK   115712               // cand k i32[256][16] (16384)
#define SM_SX   132096               // sidx i32[256]
#define SM_AX   133120               // exact A fp32[256]
#define SM_TOT  134144

__device__ float    g_sumsq;               // zeroed at load; final kernel re-zeroes
__device__ unsigned g_counts[K_CODES];
__device__ unsigned g_wb16[K_CODES * 32];  // bf16x2 of (-2*w), pairs along d
__device__ float    g_C[K_CODES];          // exact ||w_k||^2 (sequential rounded)

__device__ __forceinline__ void ldsm4(unsigned* r, unsigned addr) {
    asm volatile("ldmatrix.sync.aligned.m8n8.x4.shared.b16 {%0,%1,%2,%3}, [%4];"
                 : "=r"(r[0]), "=r"(r[1]), "=r"(r[2]), "=r"(r[3]) : "r"(addr));
}
__device__ __forceinline__ void mma16816(float* c, const unsigned* a,
                                         unsigned b0, unsigned b1) {
    asm volatile("mma.sync.aligned.m16n8k16.row.col.f32.bf16.bf16.f32 "
                 "{%0,%1,%2,%3}, {%4,%5,%6,%7}, {%8,%9}, {%0,%1,%2,%3};"
                 : "+f"(c[0]), "+f"(c[1]), "+f"(c[2]), "+f"(c[3])
                 : "r"(a[0]), "r"(a[1]), "r"(a[2]), "r"(a[3]), "r"(b0), "r"(b1));
}

// ---------------- setup: exact C_k + bf16(-2w) packed codebook ----------------
__global__ void vq_setup(const float* __restrict__ wt) {
    int k = threadIdx.x;   // 512 threads
    float s = 0.0f;
    for (int d = 0; d < DIM; d++) {
        float v = wt[k * DIM + d];
        s = __fadd_rn(s, __fmul_rn(v, v));
    }
    g_C[k] = s;
    for (int dd = 0; dd < 32; dd++) {
        __nv_bfloat162 p = __floats2bfloat162_rn(-2.0f * wt[k * DIM + 2 * dd],
                                                 -2.0f * wt[k * DIM + 2 * dd + 1]);
        g_wb16[k * 32 + dd] = *(unsigned*)&p;
    }
}

// per-n-tile score computation: 8 scores (2 m-tiles x {2 rows x 2 cols})
__device__ __forceinline__ void score_nt(int nt, const unsigned (&af)[2][4][4],
                                         unsigned sbase, const float2* sC2,
                                         int lane, float* s) {
    unsigned bf[8];
    unsigned ba = sbase + SM_B + (unsigned)(nt * 8 + (lane & 7)) * 144u
                  + (unsigned)((lane >> 3) & 3) * 16u;
    ldsm4(bf, ba);           // k 0..31
    ldsm4(bf + 4, ba + 64);  // k 32..63
    float2 cv = sC2[nt * 4 + (lane & 3)];
    float c0[4] = {cv.x, cv.y, cv.x, cv.y};
    float c1[4] = {cv.x, cv.y, cv.x, cv.y};
    #pragma unroll
    for (int kt = 0; kt < 4; kt++) {
        mma16816(c0, af[0][kt], bf[2 * kt], bf[2 * kt + 1]);
        mma16816(c1, af[1][kt], bf[2 * kt], bf[2 * kt + 1]);
    }
    s[0] = c0[0]; s[1] = c0[1]; s[2] = c0[2]; s[3] = c0[3];
    s[4] = c1[0]; s[5] = c1[1]; s[6] = c1[2]; s[7] = c1[3];
}

// ---------------- main ----------------
extern "C" __global__ void __launch_bounds__(TPB, 1)
vq_main(const float* __restrict__ in, const float* __restrict__ wt,
        float* __restrict__ out)
{
    extern __shared__ char smem[];
    const unsigned sbase = (unsigned)__cvta_generic_to_shared(smem);
    const int tid = threadIdx.x, wid = tid >> 5, lane = tid & 31;
    const int tok0 = blockIdx.x * TOKCTA;

    float*    sC   = (float*)(smem + SM_C);
    unsigned* sH   = (unsigned*)(smem + SM_H);
    unsigned* sCnt = (unsigned*)(smem + SM_CNT);
    int*      sCk  = (int*)(smem + SM_CK);
    int*      sSx  = (int*)(smem + SM_SX);
    float*    sAx  = (float*)(smem + SM_AX);

    // ---- stage: token tid -> A-tile row tid (bf16), exact A = sum x^2 ----
    {
        const int t = tok0 + tid, b = t >> 12, hw = t & 4095;
        const float* xp = in + (b << 18) + hw;
        float A = 0.0f;
        #pragma unroll
        for (int dd = 0; dd < 32; dd++) {
            float f0 = xp[(2 * dd) << 12];
            float f1 = xp[(2 * dd + 1) << 12];
            A = __fadd_rn(A, __fmul_rn(f0, f0));
            A = __fadd_rn(A, __fmul_rn(f1, f1));
            __nv_bfloat162 p = __floats2bfloat162_rn(f0, f1);
            *(unsigned*)(smem + SM_A + tid * 144 + dd * 4) = *(unsigned*)&p;
        }
        sAx[tid] = A;
    }
    // ---- stage B (bf16(-2w)) + C + zero hist/counters ----
    for (int i = tid; i < K_CODES * 32; i += TPB) {
        int k = i >> 5, dd = i & 31;
        *(unsigned*)(smem + SM_B + k * 144 + dd * 4) = g_wb16[i];
    }
    for (int i = tid; i < K_CODES; i += TPB) { sC[i] = g_C[i]; sH[i] = 0u; }
    sCnt[tid] = 0u;
    __syncthreads();

    // ---- load A fragments once (warp: tokens wid*32 .. +31) ----
    const int wbase = wid * 32;
    unsigned af[2][4][4];
    #pragma unroll
    for (int mt = 0; mt < 2; mt++)
        #pragma unroll
        for (int kt = 0; kt < 4; kt++) {
            unsigned aa = sbase + SM_A
                        + (unsigned)(wbase + mt * 16 + (lane & 15)) * 144u
                        + (unsigned)(kt * 32 + ((lane >> 4) & 1) * 16);
            ldsm4(af[mt][kt], aa);
        }

    const float2* sC2 = (const float2*)(smem + SM_C);

    // ---- pass 1: exact per-row final min of bf16 scores ----
    float rm[4] = {3.4e38f, 3.4e38f, 3.4e38f, 3.4e38f};
    for (int nt = 0; nt < 64; nt++) {
        float s[8];
        score_nt(nt, af, sbase, sC2, lane, s);
        rm[0] = fminf(rm[0], fminf(s[0], s[1]));
        rm[1] = fminf(rm[1], fminf(s[2], s[3]));
        rm[2] = fminf(rm[2], fminf(s[4], s[5]));
        rm[3] = fminf(rm[3], fminf(s[6], s[7]));
    }
    float th[4];
    #pragma unroll
    for (int i = 0; i < 4; i++) {   // reduce over the 4 lanes sharing each row
        rm[i] = fminf(rm[i], __shfl_xor_sync(0xffffffffu, rm[i], 1));
        rm[i] = fminf(rm[i], __shfl_xor_sync(0xffffffffu, rm[i], 2));
        th[i] = rm[i] + MARGIN;
    }

    // ---- pass 2: recompute identical scores, collect candidates ----
    const int r0 = lane >> 2;
    const int tA = wbase + r0, tB = tA + 8, tC = wbase + 16 + r0, tD = tC + 8;
    for (int nt = 0; nt < 64; nt++) {
        float s[8];
        score_nt(nt, af, sbase, sC2, lane, s);
        const int k0 = nt * 8 + 2 * (lane & 3);
        #define PUSH(val, thr, tok, kk)                                   \
            if ((val) < (thr)) {                                          \
                unsigned p_ = atomicAdd(&sCnt[tok], 1u);                  \
                if (p_ < CAP) sCk[(tok) * CAP + p_] = (kk);               \
            }
        PUSH(s[0], th[0], tA, k0)     PUSH(s[1], th[0], tA, k0 + 1)
        PUSH(s[2], th[1], tB, k0)     PUSH(s[3], th[1], tB, k0 + 1)
        PUSH(s[4], th[2], tC, k0)     PUSH(s[5], th[2], tC, k0 + 1)
        PUSH(s[6], th[3], tD, k0)     PUSH(s[7], th[3], tD, k0 + 1)
        #undef PUSH
    }
    __syncthreads();

    // ---- exact refinement: token tid, reference-rounded distances ----
    {
        const int t = tok0 + tid, b = t >> 12, hw = t & 4095;
        const float* xp = in + (b << 18) + hw;
        float x[DIM];
        #pragma unroll
        for (int d = 0; d < DIM; d++) x[d] = xp[d << 12];
        const float A = sAx[tid];

        float bestd = 3.4e38f;
        int   bidx  = 1 << 30;
        const unsigned cn = sCnt[tid];

        #define EXACT(kk)                                                  \
        {                                                                  \
            const float4* wr = (const float4*)(wt + (kk) * DIM);           \
            float dot = 0.0f;                                              \
            _Pragma("unroll")                                              \
            for (int q = 0; q < 16; q++) {                                 \
                float4 v = wr[q];                                          \
                dot = __fmaf_rn(x[4 * q],     v.x, dot);                   \
                dot = __fmaf_rn(x[4 * q + 1], v.y, dot);                   \
                dot = __fmaf_rn(x[4 * q + 2], v.z, dot);                   \
                dot = __fmaf_rn(x[4 * q + 3], v.w, dot);                   \
            }                                                              \
            float dist = __fadd_rn(__fadd_rn(A, -2.0f * dot), sC[kk]);     \
            if (dist < bestd || (dist == bestd && (kk) < bidx)) {          \
                bestd = dist; bidx = (kk);                                 \
            }                                                              \
        }
        if (cn <= CAP) {
            for (unsigned c = 0; c < cn; c++) { int k = sCk[tid * CAP + c]; EXACT(k) }
        } else {
            for (int k = 0; k < K_CODES; k++) EXACT(k)   // sound fallback
        }
        #undef EXACT
        sSx[tid] = bidx;
        atomicAdd(&sH[bidx], 1u);
    }
    __syncthreads();

    // ---- output (linear-view quirk) + loss partial ----
    float lsum = 0.0f;
    const long ob = (long)tok0 * DIM;
    for (int i = tid; i < TOKCTA * DIM; i += TPB) {
        int   tk = i >> 6, d = i & 63;
        int   k  = sSx[tk];
        float q  = wt[k * DIM + d];
        float xv = in[ob + i];
        out[ob + i] = q;
        float df = q - xv;
        lsum = fmaf(df, df, lsum);
    }
    #pragma unroll
    for (int o = 16; o > 0; o >>= 1) lsum += __shfl_xor_sync(0xffffffffu, lsum, o);
    float* red = (float*)(smem + SM_CK);   // candidates dead; reuse as scratch
    __syncthreads();
    if (lane == 0) red[wid] = lsum;
    __syncthreads();
    if (tid == 0) {
        float v = 0.0f;
        #pragma unroll
        for (int w = 0; w < 8; w++) v += red[w];
        atomicAdd(&g_sumsq, v);
    }
    for (int k = tid; k < K_CODES; k += TPB) {
        unsigned c = sH[k];
        if (c) atomicAdd(&g_counts[k], c);
    }
}

// ---------------- final: loss + perplexity + replay reset ----------------
__global__ void vq_final_kernel(float* __restrict__ out) {
    int t = threadIdx.x;  // 512 threads
    float p    = (float)g_counts[t] * (1.0f / (float)N_TOK);
    float term = p * logf(p + 1e-10f);
    #pragma unroll
    for (int o = 16; o > 0; o >>= 1) term += __shfl_xor_sync(0xffffffffu, term, o);
    __shared__ float r[16];
    if ((t & 31) == 0) r[t >> 5] = term;
    __syncthreads();
    if (t < 16) {
        float v = r[t];
        #pragma unroll
        for (int o = 8; o > 0; o >>= 1) v += __shfl_xor_sync(0x0000ffffu, v, o);
        if (t == 0) {
            out[M_ELEMS]     = 1.25f * (g_sumsq * (1.0f / (float)M_ELEMS));
            out[M_ELEMS + 1] = expf(-v);
            g_sumsq = 0.0f;
        }
    }
    g_counts[t] = 0u;
}

extern "C" void kernel_launch(void* const* d_in, const int* in_sizes, int n_in,
                              void* d_out, int out_size)
{
    const float* in  = (const float*)d_in[0];
    const float* wt  = (const float*)d_in[1];
    float*       out = (float*)d_out;

    cudaFuncSetAttribute(vq_main, cudaFuncAttributeMaxDynamicSharedMemorySize, SM_TOT);

    vq_setup<<<1, 512>>>(wt);
    vq_main<<<NCTA, TPB, SM_TOT>>>(in, wt, out);
    vq_final_kernel<<<1, 512>>>(out);
}